// round 3
// baseline (speedup 1.0000x reference)
#include <cuda_runtime.h>
#include <cstdint>
#include <cstddef>

#define T_TOKENS 4096
#define DM 2048
#define DH 1408
#define NE 32
#define NS 2
#define TOPK 6
#define NPASS 34
#define RPAIRS (T_TOKENS * TOPK)          /* 24576 routed pairs */
#define NSLOTS (RPAIRS + NS * T_TOKENS)   /* 32768 total slots  */

#define BM 128
#define BN 128
#define BK 32
#define PAD 8

// ---------------- scratch (static device globals; no allocations) ----------
__device__ float g_H[(size_t)NSLOTS * DH];     // hidden activations, fp32
__device__ float g_gates[T_TOKENS * NE];       // dense gates
__device__ int   g_tok[RPAIRS];                // token id per routed pair
__device__ float g_gate[RPAIRS];               // gate per routed pair
__device__ int   g_cnt[NE];
__device__ int   g_off[NE];
__device__ int   g_cur[NE];
__device__ int   g_passcnt[NPASS];

// ---------------- helpers ---------------------------------------------------
__device__ __forceinline__ uint32_t f2tf32(float x) {
    uint32_t r;
    asm("cvt.rna.tf32.f32 %0, %1;" : "=r"(r) : "f"(x));
    return r;
}

__device__ __forceinline__ void mma_tf32(float* d, const uint32_t* a,
                                         uint32_t b0, uint32_t b1) {
    asm("mma.sync.aligned.m16n8k8.row.col.f32.tf32.tf32.f32 "
        "{%0,%1,%2,%3}, {%4,%5,%6,%7}, {%8,%9}, {%0,%1,%2,%3};"
        : "+f"(d[0]), "+f"(d[1]), "+f"(d[2]), "+f"(d[3])
        : "r"(a[0]), "r"(a[1]), "r"(a[2]), "r"(a[3]), "r"(b0), "r"(b1));
}

// ---------------- small kernels ---------------------------------------------
__global__ void zero_kernel() {
    if (threadIdx.x < NE) g_cnt[threadIdx.x] = 0;
}

__global__ void router_kernel(const float* __restrict__ x,
                              const float* __restrict__ rw,   // [DM][NE]
                              const float* __restrict__ rb) { // [NE]
    int gw   = (blockIdx.x * blockDim.x + threadIdx.x) >> 5;  // token
    int lane = threadIdx.x & 31;                              // expert
    if (gw >= T_TOKENS) return;
    const float* xr = x + (size_t)gw * DM;
    float acc = __ldg(rb + lane);
    for (int k = 0; k < DM; k += 4) {
        float4 xv = *reinterpret_cast<const float4*>(xr + k);
        acc = fmaf(xv.x, __ldg(rw + (k + 0) * NE + lane), acc);
        acc = fmaf(xv.y, __ldg(rw + (k + 1) * NE + lane), acc);
        acc = fmaf(xv.z, __ldg(rw + (k + 2) * NE + lane), acc);
        acc = fmaf(xv.w, __ldg(rw + (k + 3) * NE + lane), acc);
    }
    // softmax across the 32 lanes
    float m = acc;
    for (int o = 16; o; o >>= 1) m = fmaxf(m, __shfl_xor_sync(0xffffffffu, m, o));
    float e = expf(acc - m);
    float s = e;
    for (int o = 16; o; o >>= 1) s += __shfl_xor_sync(0xffffffffu, s, o);
    float p = e / s;
    // iterative top-6 (tie-break: lower index, matching lax.top_k)
    float pv = p, sum6 = 0.0f;
    bool sel = false;
    #pragma unroll
    for (int j = 0; j < TOPK; j++) {
        float v = pv; int idx = lane;
        for (int o = 16; o; o >>= 1) {
            float ov = __shfl_xor_sync(0xffffffffu, v, o);
            int   oi = __shfl_xor_sync(0xffffffffu, idx, o);
            if (ov > v || (ov == v && oi < idx)) { v = ov; idx = oi; }
        }
        sum6 += v;
        if (lane == idx) { pv = -1.0f; sel = true; }
    }
    float gate = sel ? (p / sum6) : 0.0f;
    g_gates[gw * NE + lane] = gate;
    if (sel) atomicAdd(&g_cnt[lane], 1);
}

__global__ void scan_kernel() {
    int lane = threadIdx.x;
    int c = (lane < NE) ? g_cnt[lane] : 0;
    int s = c;
    for (int o = 1; o < 32; o <<= 1) {
        int v = __shfl_up_sync(0xffffffffu, s, o);
        if (lane >= o) s += v;
    }
    if (lane < NE) {
        g_off[lane] = s - c;
        g_cur[lane] = 0;
        g_passcnt[lane] = c;
    }
    if (lane < NS) g_passcnt[NE + lane] = T_TOKENS;
}

__global__ void pairs_kernel() {
    int idx = blockIdx.x * blockDim.x + threadIdx.x;
    if (idx >= T_TOKENS * NE) return;
    int t = idx >> 5, e = idx & 31;
    float gate = g_gates[idx];
    if (gate > 0.0f) {
        int pos = atomicAdd(&g_cur[e], 1);
        g_tok[g_off[e] + pos]  = t;
        g_gate[g_off[e] + pos] = gate;
    }
}

// ---------------- fused expert GEMM ------------------------------------------
// MODE 0: H = relu(gather(X) @ W1 + b1)   K=DM, N=DH, out -> g_H
// MODE 1: out += gate * (H @ W2 + b2)     K=DH, N=DM, atomic scatter
template <int MODE>
__global__ __launch_bounds__(256, 1)
void moe_gemm(const float* __restrict__ Xg,
              const float* __restrict__ RW, const float* __restrict__ RB,
              const float* __restrict__ SW, const float* __restrict__ SB,
              float* __restrict__ OUT) {
    constexpr int K = MODE ? DH : DM;
    constexpr int N = MODE ? DM : DH;

    const int p   = blockIdx.z;
    const int cnt = g_passcnt[p];
    const int m0  = blockIdx.y * BM;
    if (m0 >= cnt) return;                 // uniform early exit
    const int n0  = blockIdx.x * BN;

    const bool routed = (p < NE);
    const int  sidx   = routed ? 0 : (p - NE);
    const int  base   = routed ? g_off[p] : (RPAIRS + sidx * T_TOKENS);
    const float* W    = routed ? (RW + (size_t)p * K * N) : (SW + (size_t)sidx * K * N);
    const float* Bv   = routed ? (RB + (size_t)p * N)     : (SB + (size_t)sidx * N);

    __shared__ uint32_t As[BK][BM + PAD];  // A stored [k][m] (transposed)
    __shared__ uint32_t Bs[BK][BN + PAD];  // B stored [k][n]

    const int tid = threadIdx.x;

    // ---- A loader mapping: thread -> (row in tile, 16-float k-chunk)
    const int ar  = tid & 127;
    const int akc = (tid >> 7) * 16;
    const float* srcA;
    if (MODE == 0) {
        int i = m0 + ar;
        int tok;
        if (routed) {
            int ie = (i < cnt) ? i : (cnt - 1);
            tok = g_tok[base + ie];
        } else {
            tok = i;                       // shared expert: identity gather
        }
        srcA = Xg + (size_t)tok * DM;
    } else {
        srcA = g_H + (size_t)(base + m0 + ar) * DH;   // contiguous slots
    }

    // ---- B loader mapping: thread -> (k row, 16-float n-chunk)
    const int bkr = tid >> 3;
    const int bnc = (tid & 7) * 16;

    // ---- warp / fragment coordinates
    const int wid  = tid >> 5;
    const int lane = tid & 31;
    const int wm = (wid & 3) * 32;         // 4 warps along M
    const int wn = (wid >> 2) * 64;        // 2 warps along N
    const int fg = lane >> 2;              // group id 0..7
    const int ft = lane & 3;               // thread-in-group 0..3

    float acc[2][8][4];
    #pragma unroll
    for (int a = 0; a < 2; a++)
        #pragma unroll
        for (int b = 0; b < 8; b++)
            #pragma unroll
            for (int c = 0; c < 4; c++) acc[a][b][c] = 0.0f;

    float4 pa[4], pb[4];
    {   // prefetch k-tile 0
        const float* a = srcA + akc;
        pa[0] = *reinterpret_cast<const float4*>(a + 0);
        pa[1] = *reinterpret_cast<const float4*>(a + 4);
        pa[2] = *reinterpret_cast<const float4*>(a + 8);
        pa[3] = *reinterpret_cast<const float4*>(a + 12);
        const float* b = W + (size_t)bkr * N + n0 + bnc;
        pb[0] = *reinterpret_cast<const float4*>(b + 0);
        pb[1] = *reinterpret_cast<const float4*>(b + 4);
        pb[2] = *reinterpret_cast<const float4*>(b + 8);
        pb[3] = *reinterpret_cast<const float4*>(b + 12);
    }

    for (int kt = 0; kt < K; kt += BK) {
        __syncthreads();
        // store prefetched tile to smem (convert to tf32, round-to-nearest)
        #pragma unroll
        for (int j = 0; j < 4; j++) {
            float4 v = pa[j];
            As[akc + j * 4 + 0][ar] = f2tf32(v.x);
            As[akc + j * 4 + 1][ar] = f2tf32(v.y);
            As[akc + j * 4 + 2][ar] = f2tf32(v.z);
            As[akc + j * 4 + 3][ar] = f2tf32(v.w);
        }
        #pragma unroll
        for (int j = 0; j < 4; j++) {
            float4 v = pb[j];
            Bs[bkr][bnc + j * 4 + 0] = f2tf32(v.x);
            Bs[bkr][bnc + j * 4 + 1] = f2tf32(v.y);
            Bs[bkr][bnc + j * 4 + 2] = f2tf32(v.z);
            Bs[bkr][bnc + j * 4 + 3] = f2tf32(v.w);
        }
        __syncthreads();

        if (kt + BK < K) {                 // prefetch next tile (overlaps mma)
            const float* a = srcA + kt + BK + akc;
            pa[0] = *reinterpret_cast<const float4*>(a + 0);
            pa[1] = *reinterpret_cast<const float4*>(a + 4);
            pa[2] = *reinterpret_cast<const float4*>(a + 8);
            pa[3] = *reinterpret_cast<const float4*>(a + 12);
            const float* b = W + (size_t)(kt + BK + bkr) * N + n0 + bnc;
            pb[0] = *reinterpret_cast<const float4*>(b + 0);
            pb[1] = *reinterpret_cast<const float4*>(b + 4);
            pb[2] = *reinterpret_cast<const float4*>(b + 8);
            pb[3] = *reinterpret_cast<const float4*>(b + 12);
        }

        // compute: 4 k8-steps, 2 m-frags x 8 n-frags per warp
        #pragma unroll
        for (int kk = 0; kk < 4; kk++) {
            const int kb = kk * 8;
            uint32_t af[2][4];
            #pragma unroll
            for (int mi = 0; mi < 2; mi++) {
                int r = wm + mi * 16 + fg;
                af[mi][0] = As[kb + ft][r];
                af[mi][1] = As[kb + ft][r + 8];
                af[mi][2] = As[kb + ft + 4][r];
                af[mi][3] = As[kb + ft + 4][r + 8];
            }
            #pragma unroll
            for (int nj = 0; nj < 8; nj++) {
                int c = wn + nj * 8 + fg;
                uint32_t b0 = Bs[kb + ft][c];
                uint32_t b1 = Bs[kb + ft + 4][c];
                mma_tf32(acc[0][nj], af[0], b0, b1);
                mma_tf32(acc[1][nj], af[1], b0, b1);
            }
        }
    }

    // ---- epilogue
    #pragma unroll
    for (int mi = 0; mi < 2; mi++) {
        #pragma unroll
        for (int h = 0; h < 2; h++) {      // c0/c1 = row fg, c2/c3 = row fg+8
            int rl = wm + mi * 16 + fg + h * 8;
            int i  = m0 + rl;
            bool valid = (i < cnt);
            int tok = 0; float gate = 0.0f;
            if (MODE == 1 && valid) {
                if (routed) { tok = g_tok[base + i]; gate = g_gate[base + i]; }
                else        { tok = i;               gate = 0.5f; }
            }
            #pragma unroll
            for (int nj = 0; nj < 8; nj++) {
                int col = n0 + wn + nj * 8 + 2 * ft;
                float v0 = acc[mi][nj][h * 2 + 0];
                float v1 = acc[mi][nj][h * 2 + 1];
                if (!valid) continue;
                float bb0 = __ldg(Bv + col);
                float bb1 = __ldg(Bv + col + 1);
                if (MODE == 0) {
                    float s0 = fmaxf(v0 + bb0, 0.0f);
                    float s1 = fmaxf(v1 + bb1, 0.0f);
                    float2* dst = reinterpret_cast<float2*>(
                        g_H + (size_t)(base + i) * DH + col);
                    *dst = make_float2(s0, s1);
                } else {
                    atomicAdd(&OUT[(size_t)tok * DM + col],     gate * (v0 + bb0));
                    atomicAdd(&OUT[(size_t)tok * DM + col + 1], gate * (v1 + bb1));
                }
            }
        }
    }
}

// ---------------- launch -----------------------------------------------------
extern "C" void kernel_launch(void* const* d_in, const int* in_sizes, int n_in,
                              void* d_out, int out_size) {
    const float* x        = (const float*)d_in[0];
    const float* sw1      = (const float*)d_in[1];
    const float* sb1      = (const float*)d_in[2];
    const float* sw2      = (const float*)d_in[3];
    const float* sb2      = (const float*)d_in[4];
    const float* rw1      = (const float*)d_in[5];
    const float* rb1      = (const float*)d_in[6];
    const float* rw2      = (const float*)d_in[7];
    const float* rb2      = (const float*)d_in[8];
    const float* router_w = (const float*)d_in[9];
    const float* router_b = (const float*)d_in[10];
    float* out = (float*)d_out;

    cudaMemsetAsync(out, 0, (size_t)out_size * sizeof(float));
    zero_kernel<<<1, 32>>>();
    router_kernel<<<(T_TOKENS * 32) / 256, 256>>>(x, router_w, router_b);
    scan_kernel<<<1, 32>>>();
    pairs_kernel<<<(T_TOKENS * NE) / 256, 256>>>();

    dim3 g1(DH / BN, T_TOKENS / BM, NPASS);   // (11, 32, 34)
    moe_gemm<0><<<g1, 256>>>(x, rw1, rb1, sw1, sb1, nullptr);

    dim3 g2(DM / BN, T_TOKENS / BM, NPASS);   // (16, 32, 34)
    moe_gemm<1><<<g2, 256>>>(nullptr, rw2, rb2, sw2, sb2, out);
}

// round 6
// speedup vs baseline: 1.4670x; 1.4670x over previous
#include <cuda_runtime.h>
#include <cstdint>
#include <cstddef>

#define T_TOKENS 4096
#define DM 2048
#define DH 1408
#define NE 32
#define NS 2
#define TOPK 6
#define NPASS 34
#define RPAIRS (T_TOKENS * TOPK)          /* 24576 routed pairs */
#define NSLOTS (RPAIRS + NS * T_TOKENS)   /* 32768 total slots  */

#define BM 128
#define BN 128
#define BK 32
#define SMEM_DYN 99328                     /* covers both paths */

// Detect arch-specific ('a') compilation pass: tcgen05 only exists there.
#if defined(__CUDA_ARCH_FEAT_SM103_ALL) || defined(__CUDA_ARCH_FEAT_SM100_ALL) || \
    defined(__CUDA_ARCH_SPECIFIC__) || defined(__CUDA_ARCH_FAMILY_SPECIFIC__)
#define USE_TCGEN05 1
#else
#define USE_TCGEN05 0
#endif

// ---------------- scratch (static device globals; no allocations) -----------
__device__ uint32_t g_X[(size_t)T_TOKENS * DM];          // x as tf32 bits
__device__ uint32_t g_H[(size_t)NSLOTS * DH];            // hidden acts, tf32 bits
__device__ float    g_O[(size_t)NSLOTS * DM];            // per-slot outputs
__device__ uint32_t g_WT1[(size_t)NPASS * DM * DH];      // W1^T [e][n=DH][k=DM] tf32
__device__ uint32_t g_WT2[(size_t)NPASS * DH * DM];      // W2^T [e][n=DM][k=DH] tf32
__device__ float g_gates[T_TOKENS * NE];
__device__ int   g_tok[RPAIRS];
__device__ float g_gate[RPAIRS];
__device__ int   g_slotof[T_TOKENS * TOPK];
__device__ int   g_cnt[NE];
__device__ int   g_off[NE];
__device__ int   g_cur[NE];
__device__ int   g_tcnt[T_TOKENS];
__device__ int   g_passcnt[NPASS];

// ---------------- generic PTX helpers (plain sm_80+ features only) ----------
__device__ __forceinline__ uint32_t f2tf32(float x) {
    uint32_t r;
    asm("cvt.rna.tf32.f32 %0, %1;" : "=r"(r) : "f"(x));
    return r;
}
__device__ __forceinline__ uint32_t smem_u32(const void* p) {
    uint32_t r;
    asm("{ .reg .u64 t; cvta.to.shared.u64 t, %1; cvt.u32.u64 %0, t; }"
        : "=r"(r) : "l"(p));
    return r;
}
__device__ __forceinline__ void cpa16(uint32_t dst, const void* src) {
    asm volatile("cp.async.cg.shared.global [%0], [%1], 16;"
                 :: "r"(dst), "l"(src) : "memory");
}
__device__ __forceinline__ void cpa_commit() {
    asm volatile("cp.async.commit_group;" ::: "memory");
}
template <int N>
__device__ __forceinline__ void cpa_wait() {
    asm volatile("cp.async.wait_group %0;" :: "n"(N) : "memory");
}
__device__ __forceinline__ void mma_tf32(float* d, const uint32_t* a,
                                         uint32_t b0, uint32_t b1) {
    asm("mma.sync.aligned.m16n8k8.row.col.f32.tf32.tf32.f32 "
        "{%0,%1,%2,%3}, {%4,%5,%6,%7}, {%8,%9}, {%0,%1,%2,%3};"
        : "+f"(d[0]), "+f"(d[1]), "+f"(d[2]), "+f"(d[3])
        : "r"(a[0]), "r"(a[1]), "r"(a[2]), "r"(a[3]), "r"(b0), "r"(b1));
}

#if USE_TCGEN05
// ---------------- tcgen05 helpers (arch-specific pass only) -----------------
__device__ __forceinline__ bool elect_one() {
    uint32_t pred;
    asm volatile("{\n\t.reg .pred p;\n\telect.sync _|p, 0xFFFFFFFF;\n\t"
                 "selp.b32 %0, 1, 0, p;\n\t}" : "=r"(pred));
    return pred != 0;
}
__device__ __forceinline__ void mbar_init(uint32_t a, uint32_t c) {
    asm volatile("mbarrier.init.shared.b64 [%0], %1;" :: "r"(a), "r"(c) : "memory");
}
__device__ __forceinline__ void mbar_inval(uint32_t a) {
    asm volatile("mbarrier.inval.shared.b64 [%0];" :: "r"(a) : "memory");
}
__device__ __forceinline__ void mbar_wait(uint32_t a, int parity) {
    asm volatile("{\n\t.reg .pred P;\n\tW_%=:\n\t"
                 "mbarrier.try_wait.parity.acquire.cta.shared::cta.b64 P, [%0], %1, 0x989680;\n\t"
                 "@!P bra W_%=;\n\t}" :: "r"(a), "r"(parity) : "memory");
}
__device__ __forceinline__ void tc_alloc(uint32_t dst, uint32_t ncols) {
    asm volatile("tcgen05.alloc.cta_group::1.sync.aligned.shared::cta.b32 [%0], %1;"
                 :: "r"(dst), "r"(ncols) : "memory");
}
__device__ __forceinline__ void tc_relinq() {
    asm volatile("tcgen05.relinquish_alloc_permit.cta_group::1.sync.aligned;");
}
__device__ __forceinline__ void tc_dealloc(uint32_t tmem, uint32_t ncols) {
    asm volatile("tcgen05.dealloc.cta_group::1.sync.aligned.b32 %0, %1;"
                 :: "r"(tmem), "r"(ncols));
}
__device__ __forceinline__ void tc_commit(uint32_t mbar) {
    asm volatile("tcgen05.commit.cta_group::1.mbarrier::arrive::one.shared::cluster.b64 [%0];"
                 :: "r"(mbar) : "memory");
}
__device__ __forceinline__ void tc_fence_after() {
    asm volatile("tcgen05.fence::after_thread_sync;" ::: "memory");
}
__device__ __forceinline__ void tc_fence_before() {
    asm volatile("tcgen05.fence::before_thread_sync;" ::: "memory");
}
__device__ __forceinline__ void tc_wait_ld() {
    asm volatile("tcgen05.wait::ld.sync.aligned;" ::: "memory");
}
__device__ __forceinline__ void fence_async_smem() {
    asm volatile("fence.proxy.async.shared::cta;" ::: "memory");
}
__device__ __forceinline__ void mma_ss_tf32(uint32_t d, uint64_t ad, uint64_t bd,
                                            uint32_t idesc, uint32_t en) {
    asm volatile("{\n\t.reg .pred p;\n\tsetp.ne.u32 p, %4, 0;\n\t"
                 "tcgen05.mma.cta_group::1.kind::tf32 [%0], %1, %2, %3, {%5,%5,%5,%5}, p;\n\t}"
                 :: "r"(d), "l"(ad), "l"(bd), "r"(idesc), "r"(en), "r"(0u)
                 : "memory");
}
#define LDTM_X32(r, addr)                                                      \
    asm volatile("tcgen05.ld.sync.aligned.32x32b.x32.b32 "                     \
        "{%0, %1, %2, %3, %4, %5, %6, %7, "                                    \
        " %8, %9, %10, %11, %12, %13, %14, %15, "                              \
        " %16, %17, %18, %19, %20, %21, %22, %23, "                            \
        " %24, %25, %26, %27, %28, %29, %30, %31}, [%32];"                     \
        : "=r"((r)[0]),  "=r"((r)[1]),  "=r"((r)[2]),  "=r"((r)[3]),           \
          "=r"((r)[4]),  "=r"((r)[5]),  "=r"((r)[6]),  "=r"((r)[7]),           \
          "=r"((r)[8]),  "=r"((r)[9]),  "=r"((r)[10]), "=r"((r)[11]),          \
          "=r"((r)[12]), "=r"((r)[13]), "=r"((r)[14]), "=r"((r)[15]),          \
          "=r"((r)[16]), "=r"((r)[17]), "=r"((r)[18]), "=r"((r)[19]),          \
          "=r"((r)[20]), "=r"((r)[21]), "=r"((r)[22]), "=r"((r)[23]),          \
          "=r"((r)[24]), "=r"((r)[25]), "=r"((r)[26]), "=r"((r)[27]),          \
          "=r"((r)[28]), "=r"((r)[29]), "=r"((r)[30]), "=r"((r)[31])           \
        : "r"(addr))

// idesc: dtype f32=1<<4, atype tf32=2<<7, btype tf32=2<<10, N/8<<17, M/16<<24
#define IDESC_TF32 ((1u << 4) | (2u << 7) | (2u << 10) | ((BN / 8) << 17) | ((BM / 16) << 24))

__device__ __forceinline__ uint64_t mk_desc(uint32_t addr) {
    // K-major SW128: layout=2, version=1, SBO=64, LBO=1
    return ((2ULL << 61) | (1ULL << 46) | (64ULL << 32) | (1ULL << 16))
           | ((uint64_t)(addr >> 4) & 0x3FFF);
}
__device__ __forceinline__ uint32_t swz(uint32_t off) {
    return off ^ ((off >> 3) & 0x70);
}
#endif  // USE_TCGEN05

// ---------------- weight transpose + tf32 round -------------------------------
template <int WHICH>
__global__ void transpose_w(const float* __restrict__ R, const float* __restrict__ S) {
    constexpr int K = WHICH ? DH : DM;
    constexpr int N = WHICH ? DM : DH;
    const int e = blockIdx.z;
    const float* src = (e < NE) ? (R + (size_t)e * K * N)
                                : (S + (size_t)(e - NE) * K * N);
    uint32_t* dst = (WHICH ? g_WT2 : g_WT1) + (size_t)e * (size_t)K * N;
    __shared__ float tile[32][33];
    const int n0 = blockIdx.x * 32, k0 = blockIdx.y * 32;
    #pragma unroll
    for (int i = threadIdx.y; i < 32; i += 8)
        tile[i][threadIdx.x] = src[(size_t)(k0 + i) * N + n0 + threadIdx.x];
    __syncthreads();
    #pragma unroll
    for (int i = threadIdx.y; i < 32; i += 8)
        dst[(size_t)(n0 + i) * K + k0 + threadIdx.x] = f2tf32(tile[threadIdx.x][i]);
}

__global__ void xconv_kernel(const float* __restrict__ x) {
    size_t i = ((size_t)blockIdx.x * blockDim.x + threadIdx.x) * 4;
    float4 v = *reinterpret_cast<const float4*>(x + i);
    uint4 o;
    o.x = f2tf32(v.x); o.y = f2tf32(v.y); o.z = f2tf32(v.z); o.w = f2tf32(v.w);
    *reinterpret_cast<uint4*>(g_X + i) = o;
}

// ---------------- small kernels ------------------------------------------------
__global__ void zero_kernel() {
    int idx = blockIdx.x * blockDim.x + threadIdx.x;
    if (idx < T_TOKENS) g_tcnt[idx] = 0;
    if (idx < NE) g_cnt[idx] = 0;
}

__global__ void router_kernel(const float* __restrict__ x,
                              const float* __restrict__ rw,
                              const float* __restrict__ rb) {
    int gw   = (blockIdx.x * blockDim.x + threadIdx.x) >> 5;
    int lane = threadIdx.x & 31;
    if (gw >= T_TOKENS) return;
    const float* xr = x + (size_t)gw * DM;
    float acc = __ldg(rb + lane);
    for (int k = 0; k < DM; k += 4) {
        float4 xv = *reinterpret_cast<const float4*>(xr + k);
        acc = fmaf(xv.x, __ldg(rw + (k + 0) * NE + lane), acc);
        acc = fmaf(xv.y, __ldg(rw + (k + 1) * NE + lane), acc);
        acc = fmaf(xv.z, __ldg(rw + (k + 2) * NE + lane), acc);
        acc = fmaf(xv.w, __ldg(rw + (k + 3) * NE + lane), acc);
    }
    float m = acc;
    for (int o = 16; o; o >>= 1) m = fmaxf(m, __shfl_xor_sync(0xffffffffu, m, o));
    float e = expf(acc - m);
    float s = e;
    for (int o = 16; o; o >>= 1) s += __shfl_xor_sync(0xffffffffu, s, o);
    float p = e / s;
    float pv = p, sum6 = 0.0f;
    bool sel = false;
    #pragma unroll
    for (int j = 0; j < TOPK; j++) {
        float v = pv; int idx = lane;
        for (int o = 16; o; o >>= 1) {
            float ov = __shfl_xor_sync(0xffffffffu, v, o);
            int   oi = __shfl_xor_sync(0xffffffffu, idx, o);
            if (ov > v || (ov == v && oi < idx)) { v = ov; idx = oi; }
        }
        sum6 += v;
        if (lane == idx) { pv = -1.0f; sel = true; }
    }
    float gate = sel ? (p / sum6) : 0.0f;
    g_gates[gw * NE + lane] = gate;
    if (sel) atomicAdd(&g_cnt[lane], 1);
}

__global__ void scan_kernel() {
    int lane = threadIdx.x;
    int c = (lane < NE) ? g_cnt[lane] : 0;
    int s = c;
    for (int o = 1; o < 32; o <<= 1) {
        int v = __shfl_up_sync(0xffffffffu, s, o);
        if (lane >= o) s += v;
    }
    if (lane < NE) { g_off[lane] = s - c; g_cur[lane] = 0; g_passcnt[lane] = c; }
    if (lane < NS) g_passcnt[NE + lane] = T_TOKENS;
}

__global__ void pairs_kernel() {
    int idx = blockIdx.x * blockDim.x + threadIdx.x;
    if (idx >= T_TOKENS * NE) return;
    int t = idx >> 5, e = idx & 31;
    float gate = g_gates[idx];
    if (gate > 0.0f) {
        int pos  = atomicAdd(&g_cur[e], 1);
        int slot = g_off[e] + pos;
        g_tok[slot]  = t;
        g_gate[slot] = gate;
        int j = atomicAdd(&g_tcnt[t], 1);
        g_slotof[t * TOPK + j] = slot;
    }
}

// ---------------- expert GEMM (dual path) --------------------------------------
// MODE 0: g_H = tf32(relu(gather(g_X) @ W1 + b1))   K=DM, N=DH
// MODE 1: g_O[slot] = gate * (g_H @ W2 + b2)        K=DH, N=DM
template <int MODE>
__global__ __launch_bounds__(256, 2)
void moe_gemm_tc(const float* __restrict__ RB, const float* __restrict__ SB) {
    constexpr int K   = MODE ? DH : DM;
    constexpr int N   = MODE ? DM : DH;
    constexpr int NIT = K / BK;

    const int p   = blockIdx.z;
    const int cnt = g_passcnt[p];
    const int m0  = blockIdx.y * BM;
    if (m0 >= cnt) return;
    const int n0  = blockIdx.x * BN;

    const bool routed = (p < NE);
    const int  base   = routed ? g_off[p] : (RPAIRS + (p - NE) * T_TOKENS);
    const uint32_t* WT = (MODE ? g_WT2 : g_WT1) + (size_t)p * (size_t)K * N;
    const float*    Bv = routed ? (RB + (size_t)p * N) : (SB + (size_t)(p - NE) * N);

    extern __shared__ uint8_t dsm[];
    __shared__ float s_bias[BN];

    const int tid  = threadIdx.x;
    const int wid  = tid >> 5;
    const int lane = tid & 31;

    if (tid < BN) s_bias[tid] = __ldg(Bv + n0 + tid);

    // loader coords: thread -> row r (0..127), 4 chunks of 16B starting at cb
    const int r  = tid & 127;
    const int cb = (tid >> 7) * 4;
    const uint32_t* srcA;
    if (MODE == 0) {
        int i   = m0 + r;
        int tok = routed ? g_tok[base + (i < cnt ? i : cnt - 1)] : i;
        srcA = g_X + (size_t)tok * DM;
    } else {
        srcA = g_H + (size_t)(base + m0 + r) * DH;
    }
    const uint32_t* srcB = WT + (size_t)(n0 + r) * K;

    // warp / fragment coords (shared by both epilogues / fallback compute)
    const int wm = (wid & 3) * 32;
    const int wn = (wid >> 2) * 64;
    const int fg = lane >> 2;
    const int ft = lane & 3;

#if USE_TCGEN05
    // ===================== tcgen05 path (3-stage cp.async ring) ==============
    __shared__ uint32_t s_tmem;
    __shared__ uint64_t s_mbar[3];

    const uint32_t sb = (smem_u32(dsm) + 1023u) & ~1023u;
    uint32_t Abuf[3], Bbuf[3];
    uint64_t ad[3], bd[3];
    #pragma unroll
    for (int s = 0; s < 3; s++) {
        Abuf[s] = sb + s * 32768u;
        Bbuf[s] = sb + s * 32768u + 16384u;
        ad[s] = mk_desc(Abuf[s]);
        bd[s] = mk_desc(Bbuf[s]);
    }

    if (wid == 0) { tc_alloc(smem_u32(&s_tmem), 128); tc_relinq(); }
    if (tid == 0) {
        mbar_init(smem_u32(&s_mbar[0]), 1);
        mbar_init(smem_u32(&s_mbar[1]), 1);
        mbar_init(smem_u32(&s_mbar[2]), 1);
    }
    __syncthreads();
    const uint32_t tmem = s_tmem;
    const uint32_t mb[3] = { smem_u32(&s_mbar[0]), smem_u32(&s_mbar[1]),
                             smem_u32(&s_mbar[2]) };
    int ph[3] = {0, 0, 0};

    // copy stage: 4 A-chunks + 4 B-chunks per thread into swizzled buffers
    auto do_copy = [&](int it, int buf) {
        const int kt = it * BK;
        #pragma unroll
        for (int c = 0; c < 4; c++) {
            uint32_t off = swz((uint32_t)(r * 128 + (cb + c) * 16));
            cpa16(Abuf[buf] + off, srcA + kt + (cb + c) * 4);
        }
        #pragma unroll
        for (int c = 0; c < 4; c++) {
            uint32_t off = swz((uint32_t)(r * 128 + (cb + c) * 16));
            cpa16(Bbuf[buf] + off, srcB + kt + (cb + c) * 4);
        }
        cpa_commit();
    };

    do_copy(0, 0);
    do_copy(1, 1);

    for (int it = 0; it < NIT; ++it) {
        const int buf = it % 3;
        if (it + 1 < NIT) cpa_wait<1>(); else cpa_wait<0>();
        fence_async_smem();
        __syncthreads();
        if (wid == 0 && elect_one()) {
            #pragma unroll
            for (int s = 0; s < 4; s++)
                mma_ss_tf32(tmem, ad[buf] + 2 * s, bd[buf] + 2 * s, IDESC_TF32,
                            (it > 0 || s > 0) ? 1u : 0u);
            tc_commit(mb[buf]);
        }
        if (it + 2 < NIT) {
            const int nb = (it + 2) % 3;
            if (it >= 1) { mbar_wait(mb[nb], ph[nb]); ph[nb] ^= 1; }
            do_copy(it + 2, nb);
        }
    }
    {   // final commit tracks ALL prior MMAs
        const int lb = (NIT - 1) % 3;
        mbar_wait(mb[lb], ph[lb]);
    }
    tc_fence_after();

    // epilogue: warp w -> rows (w&3)*32+lane, cols [(w>>2)*64, +64)
    const int sub = wid & 3;
    const int ch  = (wid >> 2) * 64;
    uint32_t d0[32], d1[32];
    LDTM_X32(d0, tmem + ch);
    LDTM_X32(d1, tmem + ch + 32);
    tc_wait_ld();

    const int i = m0 + sub * 32 + lane;
    if (i < cnt) {
        if (MODE == 0) {
            uint32_t* dst = g_H + (size_t)(base + i) * DH + n0 + ch;
            #pragma unroll
            for (int c0 = 0; c0 < 64; c0 += 4) {
                const uint32_t* dr = (c0 < 32) ? d0 : d1;
                const int cc = c0 & 31;
                uint4 o;
                o.x = f2tf32(fmaxf(__uint_as_float(dr[cc + 0]) + s_bias[ch + c0 + 0], 0.f));
                o.y = f2tf32(fmaxf(__uint_as_float(dr[cc + 1]) + s_bias[ch + c0 + 1], 0.f));
                o.z = f2tf32(fmaxf(__uint_as_float(dr[cc + 2]) + s_bias[ch + c0 + 2], 0.f));
                o.w = f2tf32(fmaxf(__uint_as_float(dr[cc + 3]) + s_bias[ch + c0 + 3], 0.f));
                *reinterpret_cast<uint4*>(dst + c0) = o;
            }
        } else {
            const float gate = routed ? g_gate[base + i] : (1.0f / NS);
            float* dst = g_O + (size_t)(base + i) * DM + n0 + ch;
            #pragma unroll
            for (int c0 = 0; c0 < 64; c0 += 4) {
                const uint32_t* dr = (c0 < 32) ? d0 : d1;
                const int cc = c0 & 31;
                float4 o;
                o.x = gate * (__uint_as_float(dr[cc + 0]) + s_bias[ch + c0 + 0]);
                o.y = gate * (__uint_as_float(dr[cc + 1]) + s_bias[ch + c0 + 1]);
                o.z = gate * (__uint_as_float(dr[cc + 2]) + s_bias[ch + c0 + 2]);
                o.w = gate * (__uint_as_float(dr[cc + 3]) + s_bias[ch + c0 + 3]);
                *reinterpret_cast<float4*>(dst + c0) = o;
            }
        }
    }

    tc_fence_before();
    __syncthreads();
    if (wid == 0) {
        if (lane == 0) { mbar_inval(mb[0]); mbar_inval(mb[1]); mbar_inval(mb[2]); }
        tc_dealloc(tmem, 128);
    }

#else
    // ===================== fallback: mma.sync tf32, 2-stage cp.async =========
    // smem layout per stage: A[128][36] u32 then B[128][36] u32 (row pad = 4)
    constexpr int RS = BK + 4;                     // row stride in u32 (36)
    constexpr uint32_t STG = 2u * 128u * RS * 4u;  // stage bytes (36864)
    const uint32_t sbase = smem_u32(dsm);
    uint32_t* Sm = reinterpret_cast<uint32_t*>(dsm);

    float acc[2][8][4];
    #pragma unroll
    for (int a = 0; a < 2; a++)
        #pragma unroll
        for (int b = 0; b < 8; b++)
            #pragma unroll
            for (int c = 0; c < 4; c++) acc[a][b][c] = 0.0f;

    auto do_copy = [&](int it, int buf) {
        const int kt = it * BK;
        const uint32_t abase = sbase + buf * STG;
        const uint32_t bbase = abase + 128u * RS * 4u;
        #pragma unroll
        for (int c = 0; c < 4; c++)
            cpa16(abase + (uint32_t)(r * RS + (cb + c) * 4) * 4u,
                  srcA + kt + (cb + c) * 4);
        #pragma unroll
        for (int c = 0; c < 4; c++)
            cpa16(bbase + (uint32_t)(r * RS + (cb + c) * 4) * 4u,
                  srcB + kt + (cb + c) * 4);
        cpa_commit();
    };

    do_copy(0, 0);
    for (int it = 0; it < NIT; ++it) {
        const int buf = it & 1;
        if (it + 1 < NIT) { do_copy(it + 1, buf ^ 1); cpa_wait<1>(); }
        else              { cpa_wait<0>(); }
        __syncthreads();

        const uint32_t* As = Sm + (size_t)buf * (STG / 4);
        const uint32_t* Bs = As + 128 * RS;
        #pragma unroll
        for (int kk = 0; kk < 4; kk++) {
            const int kb = kk * 8;
            uint32_t af[2][4];
            #pragma unroll
            for (int mi = 0; mi < 2; mi++) {
                const int rr = wm + mi * 16 + fg;
                af[mi][0] = As[rr * RS + kb + ft];
                af[mi][1] = As[(rr + 8) * RS + kb + ft];
                af[mi][2] = As[rr * RS + kb + ft + 4];
                af[mi][3] = As[(rr + 8) * RS + kb + ft + 4];
            }
            #pragma unroll
            for (int nj = 0; nj < 8; nj++) {
                const int c = wn + nj * 8 + fg;
                uint32_t b0 = Bs[c * RS + kb + ft];
                uint32_t b1 = Bs[c * RS + kb + ft + 4];
                mma_tf32(acc[0][nj], af[0], b0, b1);
                mma_tf32(acc[1][nj], af[1], b0, b1);
            }
        }
        __syncthreads();
    }

    // epilogue
    #pragma unroll
    for (int mi = 0; mi < 2; mi++) {
        #pragma unroll
        for (int h = 0; h < 2; h++) {
            const int i = m0 + wm + mi * 16 + fg + h * 8;
            if (i >= cnt) continue;
            if (MODE == 0) {
                uint32_t* dst = g_H + (size_t)(base + i) * DH + n0;
                #pragma unroll
                for (int nj = 0; nj < 8; nj++) {
                    const int col = wn + nj * 8 + 2 * ft;
                    uint2 o;
                    o.x = f2tf32(fmaxf(acc[mi][nj][h * 2 + 0] + s_bias[col], 0.f));
                    o.y = f2tf32(fmaxf(acc[mi][nj][h * 2 + 1] + s_bias[col + 1], 0.f));
                    *reinterpret_cast<uint2*>(dst + col) = o;
                }
            } else {
                const float gate = routed ? g_gate[base + i] : (1.0f / NS);
                float* dst = g_O + (size_t)(base + i) * DM + n0;
                #pragma unroll
                for (int nj = 0; nj < 8; nj++) {
                    const int col = wn + nj * 8 + 2 * ft;
                    float2 o;
                    o.x = gate * (acc[mi][nj][h * 2 + 0] + s_bias[col]);
                    o.y = gate * (acc[mi][nj][h * 2 + 1] + s_bias[col + 1]);
                    *reinterpret_cast<float2*>(dst + col) = o;
                }
            }
        }
    }
#endif
}

// ---------------- final combine ------------------------------------------------
__global__ void combine_kernel(float* __restrict__ out) {
    const int t = blockIdx.x;
    const int c = threadIdx.x * 4;
    float4 acc = make_float4(0.f, 0.f, 0.f, 0.f);
    #pragma unroll
    for (int j = 0; j < TOPK; j++) {
        int slot = g_slotof[t * TOPK + j];
        float4 v = *reinterpret_cast<const float4*>(g_O + (size_t)slot * DM + c);
        acc.x += v.x; acc.y += v.y; acc.z += v.z; acc.w += v.w;
    }
    #pragma unroll
    for (int s = 0; s < NS; s++) {
        int slot = RPAIRS + s * T_TOKENS + t;
        float4 v = *reinterpret_cast<const float4*>(g_O + (size_t)slot * DM + c);
        acc.x += v.x; acc.y += v.y; acc.z += v.z; acc.w += v.w;
    }
    *reinterpret_cast<float4*>(out + (size_t)t * DM + c) = acc;
}

// ---------------- launch --------------------------------------------------------
extern "C" void kernel_launch(void* const* d_in, const int* in_sizes, int n_in,
                              void* d_out, int out_size) {
    const float* x        = (const float*)d_in[0];
    const float* sw1      = (const float*)d_in[1];
    const float* sb1      = (const float*)d_in[2];
    const float* sw2      = (const float*)d_in[3];
    const float* sb2      = (const float*)d_in[4];
    const float* rw1      = (const float*)d_in[5];
    const float* rb1      = (const float*)d_in[6];
    const float* rw2      = (const float*)d_in[7];
    const float* rb2      = (const float*)d_in[8];
    const float* router_w = (const float*)d_in[9];
    const float* router_b = (const float*)d_in[10];
    float* out = (float*)d_out;

    cudaFuncSetAttribute(moe_gemm_tc<0>, cudaFuncAttributeMaxDynamicSharedMemorySize, SMEM_DYN);
    cudaFuncSetAttribute(moe_gemm_tc<1>, cudaFuncAttributeMaxDynamicSharedMemorySize, SMEM_DYN);

    transpose_w<0><<<dim3(DH / 32, DM / 32, NPASS), dim3(32, 8)>>>(rw1, sw1);
    transpose_w<1><<<dim3(DM / 32, DH / 32, NPASS), dim3(32, 8)>>>(rw2, sw2);
    xconv_kernel<<<(T_TOKENS * DM) / (256 * 4), 256>>>(x);

    zero_kernel<<<T_TOKENS / 256, 256>>>();
    router_kernel<<<(T_TOKENS * 32) / 256, 256>>>(x, router_w, router_b);
    scan_kernel<<<1, 32>>>();
    pairs_kernel<<<(T_TOKENS * NE) / 256, 256>>>();

    dim3 g1(DH / BN, T_TOKENS / BM, NPASS);   // (11, 32, 34)
    moe_gemm_tc<0><<<g1, 256, SMEM_DYN>>>(rb1, sb1);

    dim3 g2(DM / BN, T_TOKENS / BM, NPASS);   // (16, 32, 34)
    moe_gemm_tc<1><<<g2, 256, SMEM_DYN>>>(rb2, sb2);

    combine_kernel<<<T_TOKENS, 512>>>(out);
}